// round 13
// baseline (speedup 1.0000x reference)
#include <cuda_runtime.h>
#include <cuda_fp16.h>

#define NAB 10
#define MAXN 131072
#define PREPW_BLOCKS 2560

static __device__ int g_cnt[NAB];
static __device__ int g_off[NAB+1];
static __device__ int g_cursor[NAB];
static __device__ int g_tb_s[NAB+1];
static __device__ int g_tb_v[NAB+1];
static __device__ int g_zn[MAXN];
static __device__ int g_perm[MAXN];
static __device__ int g_work;
static __device__ int g_done;
// fp16 weights: [20 mats][4 k-chunks][128 o][72 k-pad] (144B rows; pad stays 0)
static __device__ __half g_Wh[20*4*128*72];

__device__ __forceinline__ unsigned su32(const void* p){
  return (unsigned)__cvta_generic_to_shared(p);
}
__device__ __forceinline__ void ldsm4(unsigned r[4], unsigned addr){
  asm volatile("ldmatrix.sync.aligned.m8n8.x4.shared.b16 {%0,%1,%2,%3}, [%4];"
    : "=r"(r[0]),"=r"(r[1]),"=r"(r[2]),"=r"(r[3]) : "r"(addr));
}
__device__ __forceinline__ void hmma(float c[4], const unsigned a[4],
                                     unsigned b0, unsigned b1){
  asm volatile("mma.sync.aligned.m16n8k16.row.col.f32.f16.f16.f32 "
    "{%0,%1,%2,%3},{%4,%5,%6,%7},{%8,%9},{%0,%1,%2,%3};"
    : "+f"(c[0]),"+f"(c[1]),"+f"(c[2]),"+f"(c[3])
    : "r"(a[0]),"r"(a[1]),"r"(a[2]),"r"(a[3]),"r"(b0),"r"(b1));
}

// ---------- fused prep kernel (prepw + hist + last-block scan) ----------
__global__ void k_prep(const float* __restrict__ Wl0, const float* __restrict__ Wl1,
                       const float* __restrict__ Wt0, const float* __restrict__ Wt1,
                       const float* __restrict__ attrs, int N, int nblocks){
  if (blockIdx.x < PREPW_BLOCKS){
    int idx = blockIdx.x*blockDim.x + threadIdx.x;
    int mat = idx >> 15;
    int r = idx & 32767;
    int k = r >> 7, o = r & 127;
    int type = mat / 10, a = mat - type*10;
    float v;
    if (k < 128) {
      const float* W = type ? Wl1 : Wl0;
      v = W[k*128 + o] * 0.08838834764831845f;                 // LIN: 1/sqrt(128)
    } else {
      const float* W = type ? Wt1 : Wt0;
      v = W[(k-128)*1280 + a*128 + o] * 0.027950849718747373f; // TP: 1/sqrt(1280)
    }
    int kc = k >> 6, kk = k & 63;
    g_Wh[(size_t)mat*36864 + kc*9216 + o*72 + kk] = __float2half_rn(v);
  } else {
    __shared__ int s[NAB];
    if (threadIdx.x < NAB) s[threadIdx.x] = 0;
    __syncthreads();
    int n = (blockIdx.x - PREPW_BLOCKS)*blockDim.x + threadIdx.x;
    if (n < N){
      const float* p = attrs + (size_t)n*NAB;
      int a = 0; float best = p[0];
      #pragma unroll
      for (int i=1;i<NAB;++i){ float v=p[i]; if (v>best){best=v;a=i;} }
      g_zn[n] = a;
      atomicAdd(&s[a], 1);
    }
    __syncthreads();
    if (threadIdx.x < NAB) atomicAdd(&g_cnt[threadIdx.x], s[threadIdx.x]);
  }
  __syncthreads();
  if (threadIdx.x == 0){
    __threadfence();
    if (atomicAdd(&g_done, 1) == nblocks - 1){
      g_work = 0;
      g_done = 0;
      g_off[0]=0; g_tb_s[0]=0; g_tb_v[0]=0;
      for (int a=0;a<NAB;++a){
        int c = g_cnt[a];
        g_cnt[a] = 0;
        g_off[a+1]  = g_off[a] + c;
        g_cursor[a] = g_off[a];
        g_tb_s[a+1] = g_tb_s[a] + (c + 127)/128;
        g_tb_v[a+1] = g_tb_v[a] + (c + 41)/42;
      }
      __threadfence();
    }
  }
}

__global__ void k_scatter(int N){
  __shared__ int sc[NAB], sb[NAB];
  if (threadIdx.x < NAB) sc[threadIdx.x] = 0;
  __syncthreads();
  int n = blockIdx.x*blockDim.x + threadIdx.x;
  int a = 0, p = 0;
  bool valid = (n < N);
  if (valid){ a = g_zn[n]; p = atomicAdd(&sc[a], 1); }
  __syncthreads();
  if (threadIdx.x < NAB) sb[threadIdx.x] = atomicAdd(&g_cursor[threadIdx.x], sc[threadIdx.x]);
  __syncthreads();
  if (valid) g_perm[sb[a] + p] = n;
}

// ---------- GEMM helpers ----------
__device__ __forceinline__ void meta(int t, int ts_tot,
    int& isv, int& base, int& end, int& key, int& width){
  isv = (t >= ts_tot) ? 1 : 0;
  int tt = isv ? t - ts_tot : t;
  const int* tb = isv ? g_tb_v : g_tb_s;
  int a = 0;
  while (tt >= tb[a+1]) ++a;
  int tile = tt - tb[a];
  width = isv ? 42 : 128;
  base = g_off[a] + tile*width;
  end  = g_off[a+1];
  key  = (isv ? NAB : 0) + a;
}

// 256-thread gather, 8 slices split into two passes of 4
__device__ __forceinline__ void ld_slices(const float* __restrict__ src, int cb, int isv,
                                          const int nd[8], int tid, int pass, float4 pv[4]){
  if (!isv){
    #pragma unroll
    for (int i=0;i<4;++i){
      int q = tid + (pass*4+i)*256;
      int u = (q & 15) << 2;
      int node = nd[pass*4+i];
      pv[i] = (node>=0) ? *(const float4*)(src + (size_t)node*512 + cb + u)
                        : make_float4(0.f,0.f,0.f,0.f);
    }
  } else {
    #pragma unroll
    for (int i=0;i<4;++i){
      int q = tid + (pass*4+i)*256;
      int node = nd[pass*4+i];
      if (q >= 2016 || node < 0) continue;
      int ln = q/48, u = (q - ln*48) << 2;
      pv[i] = *(const float4*)(src + (size_t)node*512 + cb + u);
    }
  }
}
__device__ __forceinline__ void st_slices(char* Ad, int isv, int tid, int pass,
                                          const int nd[8], const float4 pv[4]){
  if (!isv){
    #pragma unroll
    for (int i=0;i<4;++i){
      int q = tid + (pass*4+i)*256;
      if (nd[pass*4+i] < 0) continue;
      int ln = q >> 4, u = (q & 15) << 2;
      __half2* d = (__half2*)(Ad + ln*144 + u*2);
      d[0] = __floats2half2_rn(pv[i].x, pv[i].y);
      d[1] = __floats2half2_rn(pv[i].z, pv[i].w);
    }
  } else {
    #pragma unroll
    for (int i=0;i<4;++i){
      int q = tid + (pass*4+i)*256;
      if (q >= 2016 || nd[pass*4+i] < 0) continue;
      int ln = q/48, u = (q - ln*48) << 2;
      const float vv[4] = {pv[i].x, pv[i].y, pv[i].z, pv[i].w};
      #pragma unroll
      for (int e=0;e<4;++e){
        int jr = u + e;
        int il = jr/3, x = jr - 3*il;
        *(__half*)(Ad + (3*ln + x)*144 + il*2) = __float2half_rn(vv[e]);
      }
    }
  }
}

// ---------- main GEMM: 2 CTAs/SM x 256 thr, 128x128 tiles, 32x64 warp tiles ----------
// SMEM per CTA: [0, 73728) B weights (4 chunks x [128][72h], 144B rows)
//               [73728, +36864) A double buffer (2 x [128][72h]); v-stage [128][68]f32 reuses it
#define B_BYTES 73728
#define A_SEC   18432
#define SMEM_BYTES (B_BYTES + 2*A_SEC)

__global__ void __launch_bounds__(256, 2) k_gemm(
    const float* __restrict__ Xm, const float* __restrict__ Xf,
    float* __restrict__ out){
  extern __shared__ char smem[];
  float* stage = (float*)(smem + B_BYTES);   // 128 x 68 f32 = 34816B <= 36864B
  __shared__ int snode[2][128];
  __shared__ int s_grab[2];

  const int tid  = threadIdx.x;
  const int lane = tid & 31;
  const int wid  = tid >> 5;
  const int wm = wid & 3, wn = wid >> 2;   // 4x2 warps, each 32 rows x 64 cols
  const int g4 = lane >> 2, t4 = lane & 3;
  const unsigned smb = su32(smem);
  const unsigned AbU = smb + B_BYTES;

  const int ra  = lane & 15;
  const int ca  = (lane >> 4) << 3;
  const int rb  = ((lane >> 4) & 1)*8 + (lane & 7);
  const int cb2 = ((lane >> 3) & 1) << 3;

  const int ts_tot = g_tb_s[NAB];
  const int tv_tot = g_tb_v[NAB];
  const int total  = ts_tot + tv_tot;

  if (tid == 0) s_grab[0] = atomicAdd(&g_work, 1);
  __syncthreads();
  int t = s_grab[0];
  int sp = 0, cur = -1;

  while (t < total){
    int isv, base, end, key, width;
    meta(t, ts_tot, isv, base, end, key, width);
    if (tid == 0) s_grab[sp^1] = atomicAdd(&g_work, 1);
    if (tid < width) snode[sp][tid] = (base + tid < end) ? g_perm[base + tid] : -1;

    int nd[8];
    if (!isv){
      #pragma unroll
      for (int i=0;i<8;++i){
        int slot = (tid + i*256) >> 4;
        nd[i] = (base+slot < end) ? g_perm[base+slot] : -1;
      }
    } else {
      #pragma unroll
      for (int i=0;i<8;++i){
        int q = tid + i*256;
        int slot = q/48;
        nd[i] = (q < 2016 && base+slot < end) ? g_perm[base+slot] : -1;
      }
    }
    __syncthreads();   // B0: all warps done with previous tile; snode/s_grab visible

    // Safe uniform read of the next tile id: written before B0 by tid0; this slot
    // is next rewritten only at the top of iteration i+2, which tid0 reaches only
    // after B0 of iteration i+1 — a barrier every thread crosses after this read.
    const int t_next = s_grab[sp^1];

    if (key != cur){
      cur = key;
      const float4* srcW = (const float4*)(g_Wh + (size_t)key*36864);
      float4* dstW = (float4*)smem;
      #pragma unroll 6
      for (int q = tid; q < 4608; q += 256) dstW[q] = srcW[q];
      __syncthreads();
    }

    // cold gather chunk0 -> buf0
    {
      const int cb = isv ? 128 : 0;
      #pragma unroll
      for (int p=0;p<2;++p){
        float4 pv[4];
        ld_slices(Xm, cb, isv, nd, tid, p, pv);
        st_slices(smem + B_BYTES, isv, tid, p, nd, pv);
      }
    }
    __syncthreads();   // B1: chunk0 visible

    float acc[2][8][4];
    #pragma unroll
    for (int i=0;i<2;++i)
      #pragma unroll
      for (int j=0;j<8;++j)
        #pragma unroll
        for (int e=0;e<4;++e) acc[i][j][e] = 0.f;

    #pragma unroll
    for (int kc = 0; kc < 4; ++kc){
      const unsigned Ac = AbU + (unsigned)((kc & 1)*A_SEC);
      const unsigned Bk = smb + (unsigned)(kc*A_SEC);
      char* Adst = smem + B_BYTES + ((kc+1) & 1)*A_SEC;
      const int nk = kc + 1;
      const float* psrc = (nk < 2) ? Xm : Xf;
      const int pcb = isv ? 128 + (nk & 1)*192 : (nk & 1)*64;

      #pragma unroll
      for (int half = 0; half < 2; ++half){
        float4 pv[4];
        if (kc < 3) ld_slices(psrc, pcb, isv, nd, tid, half, pv);

        #pragma unroll
        for (int ks = half*2; ks < half*2 + 2; ++ks){
          const int k0 = ks*16;
          unsigned af[2][4], bf[4][4];
          ldsm4(af[0], Ac + (unsigned)((wm*32      + ra)*144 + (k0+ca)*2));
          ldsm4(af[1], Ac + (unsigned)((wm*32 + 16 + ra)*144 + (k0+ca)*2));
          #pragma unroll
          for (int j=0;j<4;++j)
            ldsm4(bf[j], Bk + (unsigned)((wn*64 + j*16 + rb)*144 + (k0+cb2)*2));
          #pragma unroll
          for (int mi = 0; mi < 2; ++mi){
            #pragma unroll
            for (int j = 0; j < 4; ++j){
              hmma(acc[mi][2*j  ], af[mi], bf[j][0], bf[j][1]);
              hmma(acc[mi][2*j+1], af[mi], bf[j][2], bf[j][3]);
            }
          }
        }
        if (kc < 3) st_slices(Adst, isv, tid, half, nd, pv);
      }
      if (kc < 3) __syncthreads();   // STS of chunk kc+1 visible; MMA kc done
    }

    // ---- epilogue ----
    if (!isv){
      #pragma unroll
      for (int mi = 0; mi < 2; ++mi){
        int r0 = wm*32 + mi*16 + g4;
        int n0 = snode[sp][r0], n1 = snode[sp][r0+8];
        #pragma unroll
        for (int jj = 0; jj < 8; ++jj){
          int c = wn*64 + jj*8 + 2*t4;
          if (n0 >= 0)
            *(float2*)(out + (size_t)n0*512 + c) = make_float2(acc[mi][jj][0], acc[mi][jj][1]);
          if (n1 >= 0)
            *(float2*)(out + (size_t)n1*512 + c) = make_float2(acc[mi][jj][2], acc[mi][jj][3]);
        }
      }
    } else {
      __syncthreads();   // all MMA reads done — A region reusable as stage
      #pragma unroll
      for (int pc = 0; pc < 2; ++pc){
        if (pc) __syncthreads();     // pass0 stage reads done
        if (wn == pc){
          #pragma unroll
          for (int mi = 0; mi < 2; ++mi){
            int r = wm*32 + mi*16 + g4;
            #pragma unroll
            for (int jj = 0; jj < 8; ++jj){
              int lc = jj*8 + 2*t4;
              float* d1 = stage + r*68 + lc;
              d1[0] = acc[mi][jj][0]; d1[1] = acc[mi][jj][1];
              float* d2 = stage + (r+8)*68 + lc;
              d2[0] = acc[mi][jj][2]; d2[1] = acc[mi][jj][3];
            }
          }
        }
        __syncthreads();             // stage pass pc ready
        #pragma unroll
        for (int i = 0; i < 8; ++i){
          int q = tid + i*256;
          if (q >= 2016) break;
          int ln = q / 48, w = (q - ln*48) << 2;
          int node = snode[sp][ln];
          if (node < 0) continue;
          float4 v;
          float* vp = (float*)&v;
          #pragma unroll
          for (int e=0;e<4;++e){
            int jr = w + e;
            int ol = jr/3, x = jr - 3*ol;
            vp[e] = stage[(3*ln + x)*68 + ol];
          }
          *(float4*)(out + (size_t)node*512 + 128 + pc*192 + w) = v;
        }
      }
    }

    t = t_next;
    sp ^= 1;
  }
}

extern "C" void kernel_launch(void* const* d_in, const int* in_sizes, int n_in,
                              void* d_out, int out_size){
  const float* m_i   = (const float*)d_in[0];
  const float* nfeat = (const float*)d_in[1];
  const float* attrs = (const float*)d_in[2];
  const float* Wl0   = (const float*)d_in[3];
  const float* Wl1   = (const float*)d_in[4];
  const float* Wt0   = (const float*)d_in[5];
  const float* Wt1   = (const float*)d_in[6];
  float* out = (float*)d_out;
  int N = in_sizes[0] / 512;
  if (N > MAXN) return;

  cudaFuncSetAttribute(k_gemm, cudaFuncAttributeMaxDynamicSharedMemorySize, SMEM_BYTES);

  int hist_blocks = (N + 255)/256;
  int prep_blocks = PREPW_BLOCKS + hist_blocks;
  k_prep<<<prep_blocks, 256>>>(Wl0, Wl1, Wt0, Wt1, attrs, N, prep_blocks);
  k_scatter<<<hist_blocks, 256>>>(N);
  k_gemm<<<296, 256, SMEM_BYTES>>>(m_i, nfeat, out);
}